// round 3
// baseline (speedup 1.0000x reference)
#include <cuda_runtime.h>
#include <math_constants.h>

// Hausdorff distance between edge sets of two binary 128^3 masks, batch=2.
// Strategy: bit-pack masks -> bitwise 3x3x3 edge extraction -> exact 1D
// x-axis distance field g (u8, clamped) -> per edge voxel, exact 3D EDT via
// expanding-ring early-exit search over (dy,dz) using g, reduced to a
// directed max. Output: 2 floats.

#define DWH 128
#define NVOL 4                      // (b0,in) (b0,tgt) (b1,in) (b1,tgt)
#define VOXELS (128 * 128 * 128)
#define GCLAMP 222                  // 222^2 = 49284 > 3*127^2 = 48387 -> lossless

// ---- scratch: __device__ globals (no allocation allowed) ----
__device__ unsigned int g_mask[NVOL][DWH][DWH][4];    // bit-packed masks, 1MB
__device__ unsigned int g_edge[NVOL][DWH][DWH][4];    // bit-packed edges, 1MB
__device__ unsigned int g_g[NVOL][DWH][DWH][32];      // 1D x-dist u8[128] per row, 8MB
__device__ int          g_cnt[NVOL];                  // edge voxel counts
__device__ int          g_dirmax[NVOL];               // directed max of squared EDT

// ============================================================================
// Kernel 1: binarize inputs (>0) into bit-packed masks via warp ballot.
// Also zeroes the accumulators (consumed only by later kernels).
// ============================================================================
__global__ void __launch_bounds__(256) k_binarize(
    const float* __restrict__ inputs, const float* __restrict__ targets)
{
    int gt = blockIdx.x * blockDim.x + threadIdx.x;   // 8,388,608 threads
    if (gt < 8) {
        if (gt < 4) g_cnt[gt] = 0;
        else        g_dirmax[gt - 4] = 0;
    }
    int lane = gt & 31;
    int c    = gt >> 5;              // chunk id, one warp each
    int v    = c >> 16;
    int rem  = c & 65535;
    int z    = rem >> 9;
    int y    = (rem >> 2) & 127;
    int w    = rem & 3;
    int x    = (w << 5) + lane;

    const float* src = (v & 1) ? targets : inputs;
    int b = v >> 1;
    float val = src[(size_t)b * VOXELS + z * 16384 + y * 128 + x];
    unsigned int bal = __ballot_sync(0xFFFFFFFFu, val > 0.0f);
    if (lane == 0) g_mask[v][z][y][w] = bal;
}

// ============================================================================
// Kernel 2: edge = (~mask) & (3x3x3 box-OR of mask), bitwise per (v,z,y) row,
// FUSED with the exact 1D distance-to-nearest-edge along x (g, u8 clamped).
// g stays entirely in registers (fully unrolled byte-packed array).
// Also accumulates edge-voxel counts (emptiness check).
// ============================================================================
__global__ void __launch_bounds__(128) k_edge()
{
    int t = blockIdx.x * blockDim.x + threadIdx.x;    // 65536 rows
    int v = t >> 14;
    int z = (t >> 7) & 127;
    int y = t & 127;

    unsigned int a0 = 0, a1 = 0, a2 = 0, a3 = 0;
    #pragma unroll
    for (int dz = -1; dz <= 1; dz++) {
        int zz = z + dz;
        if (zz < 0 || zz > 127) continue;
        #pragma unroll
        for (int dy = -1; dy <= 1; dy++) {
            int yy = y + dy;
            if (yy < 0 || yy > 127) continue;
            const unsigned int* r = g_mask[v][zz][yy];
            a0 |= r[0]; a1 |= r[1]; a2 |= r[2]; a3 |= r[3];
        }
    }
    // dilate along x across the 128-bit row (word carries)
    unsigned int d0 = a0 | (a0 << 1)               | (a0 >> 1) | (a1 << 31);
    unsigned int d1 = a1 | (a1 << 1) | (a0 >> 31)  | (a1 >> 1) | (a2 << 31);
    unsigned int d2 = a2 | (a2 << 1) | (a1 >> 31)  | (a2 >> 1) | (a3 << 31);
    unsigned int d3 = a3 | (a3 << 1) | (a2 >> 31)  | (a3 >> 1);

    const unsigned int* m = g_mask[v][z][y];
    unsigned int ew[4];
    ew[0] = d0 & ~m[0]; ew[1] = d1 & ~m[1]; ew[2] = d2 & ~m[2]; ew[3] = d3 & ~m[3];
    unsigned int* o = g_edge[v][z][y];
    o[0] = ew[0]; o[1] = ew[1]; o[2] = ew[2]; o[3] = ew[3];

    int cnt = __popc(ew[0]) + __popc(ew[1]) + __popc(ew[2]) + __popc(ew[3]);
    #pragma unroll
    for (int off = 16; off; off >>= 1)
        cnt += __shfl_down_sync(0xFFFFFFFFu, cnt, off);
    if ((threadIdx.x & 31) == 0) atomicAdd(&g_cnt[v], cnt);  // warp covers one v

    // ---- fused 1D x-distance g (exact, clamped at GCLAMP) ----
    unsigned int gr[32];                 // 128 u8 packed, static-indexed -> regs
    {
        int g = GCLAMP;
        #pragma unroll
        for (int w4 = 0; w4 < 32; w4++) {              // packs x = 4*w4 .. +3
            unsigned int word = ew[w4 >> 3];
            unsigned int packed = 0;
            #pragma unroll
            for (int j = 0; j < 4; j++) {
                int bit = (word >> (((w4 & 7) << 2) + j)) & 1;
                g = bit ? 0 : (g < GCLAMP ? g + 1 : GCLAMP);
                packed |= (unsigned int)g << (8 * j);
            }
            gr[w4] = packed;
        }
        int p = (gr[31] >> 24) & 0xFF;
        #pragma unroll
        for (int x = 126; x >= 0; x--) {
            int w4 = x >> 2, sh = (x & 3) << 3;
            int c = (gr[w4] >> sh) & 0xFF;
            int nv = p + 1;
            if (c < nv) nv = c;                        // nv <= GCLAMP always
            gr[w4] = (gr[w4] & ~(0xFFu << sh)) | ((unsigned int)nv << sh);
            p = nv;
        }
    }
    uint4* og = (uint4*)g_g[v][z][y];
    #pragma unroll
    for (int i = 0; i < 8; i++)
        og[i] = make_uint4(gr[4*i], gr[4*i+1], gr[4*i+2], gr[4*i+3]);
}

// ============================================================================
// Kernel 3: for every edge voxel q=(x,y,z) of query volume qv, exact EDT to
// the partner pv's edge set:
//     EDT(q) = min_{yy,zz} (y-yy)^2 + (z-zz)^2 + g_pv(x,yy,zz)^2
// via expanding-ring early-exit (dz outer, dy inner; bounds shrink with best).
// Directed max reduced per block -> atomicMax(g_dirmax[qv]).
// Block = (qv, z, y-half); 128 threads = x lane.
// ============================================================================
__global__ void __launch_bounds__(128) k_query()
{
    int b  = blockIdx.x;                 // 1024 blocks
    int qv = b >> 8;
    int z  = (b >> 1) & 127;
    int yh = b & 1;
    int x  = threadIdx.x;
    int pv = qv ^ 1;

    int lmax = -1;
    if (g_cnt[pv] != 0) {                // empty partner -> output is inf anyway
        int wrd = x >> 5, sh = x & 31;
        const unsigned char* gp = (const unsigned char*)g_g[pv] + x;
        for (int yi = 0; yi < 64; yi++) {
            int y = (yh << 6) + yi;
            unsigned int eb = g_edge[qv][z][y][wrd];   // warp-uniform load
            if (!((eb >> sh) & 1)) continue;

            int best = 1 << 29;
            for (int dz = 0; dz <= 127; dz++) {
                int dz2 = dz * dz;
                if (dz2 >= best) break;
                #pragma unroll
                for (int sz = 0; sz < 2; sz++) {
                    int zz = sz ? z - dz : z + dz;
                    if ((sz & (dz == 0)) | (zz < 0) | (zz > 127)) continue;
                    const unsigned char* gz = gp + zz * 16384;
                    for (int dy = 0; dy <= 127; dy++) {
                        int c0 = dz2 + dy * dy;
                        if (c0 >= best) break;
                        int yy = y + dy;
                        if (yy <= 127) {
                            int gg  = gz[yy * 128];
                            int cst = c0 + gg * gg;
                            if (cst < best) best = cst;
                        }
                        yy = y - dy;
                        if (dy && yy >= 0) {
                            int gg  = gz[yy * 128];
                            int cst = c0 + gg * gg;
                            if (cst < best) best = cst;
                        }
                    }
                }
            }
            if (best > lmax) lmax = best;
        }
    }

    // block max over 128 threads -> one atomic per block
    #pragma unroll
    for (int off = 16; off; off >>= 1) {
        int o = __shfl_down_sync(0xFFFFFFFFu, lmax, off);
        if (o > lmax) lmax = o;
    }
    __shared__ int wmax[4];
    if ((x & 31) == 0) wmax[x >> 5] = lmax;
    __syncthreads();
    if (x == 0) {
        int m = wmax[0];
        if (wmax[1] > m) m = wmax[1];
        if (wmax[2] > m) m = wmax[2];
        if (wmax[3] > m) m = wmax[3];
        if (m >= 0) atomicMax(&g_dirmax[qv], m);
    }
}

// ============================================================================
// Kernel 4: finalize. hd[b] = sqrt(max of the two directed squared maxima),
// inf if either edge set is empty.
// ============================================================================
__global__ void k_final(float* __restrict__ out)
{
    int b = threadIdx.x;
    if (b < 2) {
        int vA = 2 * b, vB = 2 * b + 1;
        bool empty = (g_cnt[vA] == 0) || (g_cnt[vB] == 0);
        int m = g_dirmax[vA] > g_dirmax[vB] ? g_dirmax[vA] : g_dirmax[vB];
        out[b] = empty ? CUDART_INF_F : sqrtf((float)m);
    }
}

// ============================================================================
extern "C" void kernel_launch(void* const* d_in, const int* in_sizes, int n_in,
                              void* d_out, int out_size)
{
    const float* inputs  = (const float*)d_in[0];
    const float* targets = (const float*)d_in[1];
    float* out = (float*)d_out;

    k_binarize<<<32768, 256>>>(inputs, targets);
    k_edge    <<<512, 128>>>();
    k_query   <<<1024, 128>>>();
    k_final   <<<1, 32>>>(out);
}

// round 5
// speedup vs baseline: 12.6037x; 12.6037x over previous
#include <cuda_runtime.h>
#include <math_constants.h>

// Hausdorff distance between edge sets of two binary 128^3 masks, batch=2.
// Pipeline: bit-pack masks -> bitwise 3x3x3 edge extraction fused with exact
// 1D x-distance g (u8) -> Meijster envelope along y (register-cached stack
// top) producing dt2 = exact 2D squared EDT per z-slice (u16) -> per partner
// edge voxel, exact min over z with tight warp-coherent early exit -> max.
// Output: 2 floats.

#define DWH 128
#define NVOL 4                      // (b0,in) (b0,tgt) (b1,in) (b1,tgt)
#define VOXELS (128 * 128 * 128)
#define GCLAMP 222                  // 222^2 = 49284 > 3*127^2 -> lossless clamp

// ---- scratch: __device__ globals (no allocation allowed) ----
__device__ unsigned int   g_mask[NVOL][DWH][DWH][4];  // bit-packed masks, 1MB
__device__ unsigned int   g_edge[NVOL][DWH][DWH][4];  // bit-packed edges, 1MB
__device__ unsigned int   g_g[NVOL][DWH][DWH][32];    // 1D x-dist u8[128]/row, 8MB
__device__ unsigned short g_dt2[NVOL][VOXELS];        // 2D sq-EDT per slice, 16MB
__device__ int            g_cnt[NVOL];                // edge voxel counts
__device__ int            g_dirmax[NVOL];             // directed max squared EDT

// ============================================================================
// Kernel 1: binarize inputs (>0) into bit-packed masks via warp ballot.
// Also zeroes the accumulators (consumed only by later kernels).
// ============================================================================
__global__ void __launch_bounds__(256) k_binarize(
    const float* __restrict__ inputs, const float* __restrict__ targets)
{
    int gt = blockIdx.x * blockDim.x + threadIdx.x;   // 8,388,608 threads
    if (gt < 8) {
        if (gt < 4) g_cnt[gt] = 0;
        else        g_dirmax[gt - 4] = 0;
    }
    int lane = gt & 31;
    int c    = gt >> 5;              // chunk id, one warp each
    int v    = c >> 16;
    int rem  = c & 65535;
    int z    = rem >> 9;
    int y    = (rem >> 2) & 127;
    int w    = rem & 3;
    int x    = (w << 5) + lane;

    const float* src = (v & 1) ? targets : inputs;
    int b = v >> 1;
    float val = src[(size_t)b * VOXELS + z * 16384 + y * 128 + x];
    unsigned int bal = __ballot_sync(0xFFFFFFFFu, val > 0.0f);
    if (lane == 0) g_mask[v][z][y][w] = bal;
}

// ============================================================================
// Kernel 2: edge = (~mask) & (3x3x3 box-OR of mask), bitwise per (v,z,y) row,
// FUSED with the exact 1D distance-to-nearest-edge along x (g, u8 clamped).
// g stays entirely in registers (fully unrolled byte-packed array).
// Also accumulates edge-voxel counts (emptiness check).   [validated in R3]
// ============================================================================
__global__ void __launch_bounds__(128) k_edge()
{
    int t = blockIdx.x * blockDim.x + threadIdx.x;    // 65536 rows
    int v = t >> 14;
    int z = (t >> 7) & 127;
    int y = t & 127;

    unsigned int a0 = 0, a1 = 0, a2 = 0, a3 = 0;
    #pragma unroll
    for (int dz = -1; dz <= 1; dz++) {
        int zz = z + dz;
        if (zz < 0 || zz > 127) continue;
        #pragma unroll
        for (int dy = -1; dy <= 1; dy++) {
            int yy = y + dy;
            if (yy < 0 || yy > 127) continue;
            const unsigned int* r = g_mask[v][zz][yy];
            a0 |= r[0]; a1 |= r[1]; a2 |= r[2]; a3 |= r[3];
        }
    }
    // dilate along x across the 128-bit row (word carries)
    unsigned int d0 = a0 | (a0 << 1)               | (a0 >> 1) | (a1 << 31);
    unsigned int d1 = a1 | (a1 << 1) | (a0 >> 31)  | (a1 >> 1) | (a2 << 31);
    unsigned int d2 = a2 | (a2 << 1) | (a1 >> 31)  | (a2 >> 1) | (a3 << 31);
    unsigned int d3 = a3 | (a3 << 1) | (a2 >> 31)  | (a3 >> 1);

    const unsigned int* m = g_mask[v][z][y];
    unsigned int ew[4];
    ew[0] = d0 & ~m[0]; ew[1] = d1 & ~m[1]; ew[2] = d2 & ~m[2]; ew[3] = d3 & ~m[3];
    unsigned int* o = g_edge[v][z][y];
    o[0] = ew[0]; o[1] = ew[1]; o[2] = ew[2]; o[3] = ew[3];

    int cnt = __popc(ew[0]) + __popc(ew[1]) + __popc(ew[2]) + __popc(ew[3]);
    #pragma unroll
    for (int off = 16; off; off >>= 1)
        cnt += __shfl_down_sync(0xFFFFFFFFu, cnt, off);
    if ((threadIdx.x & 31) == 0) atomicAdd(&g_cnt[v], cnt);  // warp covers one v

    // ---- fused 1D x-distance g (exact, clamped at GCLAMP) ----
    unsigned int gr[32];                 // 128 u8 packed, static-indexed -> regs
    {
        int g = GCLAMP;
        #pragma unroll
        for (int w4 = 0; w4 < 32; w4++) {              // packs x = 4*w4 .. +3
            unsigned int word = ew[w4 >> 3];
            unsigned int packed = 0;
            #pragma unroll
            for (int j = 0; j < 4; j++) {
                int bit = (word >> (((w4 & 7) << 2) + j)) & 1;
                g = bit ? 0 : (g < GCLAMP ? g + 1 : GCLAMP);
                packed |= (unsigned int)g << (8 * j);
            }
            gr[w4] = packed;
        }
        int p = (gr[31] >> 24) & 0xFF;
        #pragma unroll
        for (int x = 126; x >= 0; x--) {
            int w4 = x >> 2, sh = (x & 3) << 3;
            int c = (gr[w4] >> sh) & 0xFF;
            int nv = p + 1;
            if (c < nv) nv = c;                        // nv <= GCLAMP always
            gr[w4] = (gr[w4] & ~(0xFFu << sh)) | ((unsigned int)nv << sh);
            p = nv;
        }
    }
    uint4* og = (uint4*)g_g[v][z][y];
    #pragma unroll
    for (int i = 0; i < 8; i++)
        og[i] = make_uint4(gr[4*i], gr[4*i+1], gr[4*i+2], gr[4*i+3]);
}

// ============================================================================
// Kernel 3: Meijster lower-envelope along y per (v,z,x) column.
//   dt2(x,y,z) = min_yy (y-yy)^2 + g(x,yy,z)^2   (exact 2D squared EDT)
// f(u) read straight from the global u8 g field (coalesced along x).
// Stack TOP (sq,tq,fsq) register-cached; local stack touched only on push/pop.
// Max value = 127^2 + 222^2 = 65413 < 65536 -> u16 store needs no clamp.
// ============================================================================
__global__ void __launch_bounds__(128) k_phase2()
{
    int b = blockIdx.x;                  // 512 = 4 volumes * 128 z-slices
    int v = b >> 7;
    int z = b & 127;
    int x = threadIdx.x;

    const unsigned char* grow = (const unsigned char*)g_g[v][z];  // [y][128] u8

    short          stS[128];             // stored stack below the register top
    short          stT[128];
    unsigned short stF[128];

    int q  = 0;                          // top level; stack[0..q-1] in memory
    int sq = 0, tq = 0;
    int g0 = grow[x];
    int fsq = g0 * g0;

    #pragma unroll 4
    for (int u = 1; u < 128; u++) {
        int gu = grow[u * 128 + x];
        int fu = gu * gu;
        for (;;) {
            int aa = tq - sq, bb = tq - u;
            if (aa * aa + fsq > bb * bb + fu) {       // incumbent loses at tq
                if (q == 0) { q = -1; break; }
                q--; sq = stS[q]; tq = stT[q]; fsq = stF[q];
            } else break;
        }
        if (q < 0) { q = 0; sq = u; tq = 0; fsq = fu; }
        else {
            int w = 1 + (u * u - sq * sq + fu - fsq) / (2 * (u - sq));
            if (w < 128) {
                stS[q] = (short)sq; stT[q] = (short)tq; stF[q] = (unsigned short)fsq;
                q++; sq = u; tq = w; fsq = fu;
            }
        }
    }

    unsigned short* dt = &g_dt2[v][z * 16384 + x];
    #pragma unroll 4
    for (int u = 127; u >= 0; u--) {
        int d = u - sq;
        dt[u * 128] = (unsigned short)(d * d + fsq);
        if (u == tq) {
            q--;
            if (q >= 0) { sq = stS[q]; tq = stT[q]; fsq = stF[q]; }
        }
    }
}

// ============================================================================
// Kernel 4: z-min gather. For each edge voxel q=(x,y,z) of volume qv:
//   EDT(q) = min_zz (z-zz)^2 + dt2_pv(x,y,zz)
// Initial bound = dt2 at zz=z (already the exact in-slice EDT -> tight), then
// expand dz outward with warp-coherent __any_sync early exit. Inactive lanes
// carry best=0. Directed max -> atomicMax(g_dirmax[qv]).
// Block = (qv, z); 128 threads = x. Rows with no edge bits skip (warp-uniform).
// ============================================================================
__global__ void __launch_bounds__(128) k_zmin()
{
    int b  = blockIdx.x;                 // 512
    int qv = b >> 7;
    int z  = b & 127;
    int x  = threadIdx.x;
    int pv = qv ^ 1;

    int lmax = -1;
    if (g_cnt[pv] != 0) {                // empty partner -> output is inf anyway
        int wid = x >> 5, lane = x & 31;
        for (int y = 0; y < 128; y++) {
            unsigned int eb = g_edge[qv][z][y][wid];   // warp-uniform word
            if (eb == 0) continue;                     // whole warp skips
            int act = (eb >> lane) & 1;

            const unsigned short* col = &g_dt2[pv][y * 128 + x];
            int best = act ? (int)col[z * 16384] : 0;  // dz = 0 candidate

            for (int dz = 1; dz < 128; dz++) {
                int dz2 = dz * dz;
                if (!__any_sync(0xFFFFFFFFu, dz2 < best)) break;
                int zp = z + dz, zm = z - dz;
                if (dz2 < best && zp < 128) {
                    int c = dz2 + (int)col[zp * 16384];
                    if (c < best) best = c;
                }
                if (dz2 < best && zm >= 0) {
                    int c = dz2 + (int)col[zm * 16384];
                    if (c < best) best = c;
                }
            }
            if (act && best > lmax) lmax = best;
        }
    }

    // block max over 128 threads -> one atomic per block
    #pragma unroll
    for (int off = 16; off; off >>= 1) {
        int o = __shfl_down_sync(0xFFFFFFFFu, lmax, off);
        if (o > lmax) lmax = o;
    }
    __shared__ int wmax[4];
    if ((x & 31) == 0) wmax[x >> 5] = lmax;
    __syncthreads();
    if (x == 0) {
        int m = wmax[0];
        if (wmax[1] > m) m = wmax[1];
        if (wmax[2] > m) m = wmax[2];
        if (wmax[3] > m) m = wmax[3];
        if (m >= 0) atomicMax(&g_dirmax[qv], m);
    }
}

// ============================================================================
// Kernel 5: finalize. hd[b] = sqrt(max of the two directed squared maxima),
// inf if either edge set is empty.
// ============================================================================
__global__ void k_final(float* __restrict__ out)
{
    int b = threadIdx.x;
    if (b < 2) {
        int vA = 2 * b, vB = 2 * b + 1;
        bool empty = (g_cnt[vA] == 0) || (g_cnt[vB] == 0);
        int m = g_dirmax[vA] > g_dirmax[vB] ? g_dirmax[vA] : g_dirmax[vB];
        out[b] = empty ? CUDART_INF_F : sqrtf((float)m);
    }
}

// ============================================================================
extern "C" void kernel_launch(void* const* d_in, const int* in_sizes, int n_in,
                              void* d_out, int out_size)
{
    const float* inputs  = (const float*)d_in[0];
    const float* targets = (const float*)d_in[1];
    float* out = (float*)d_out;

    k_binarize<<<32768, 256>>>(inputs, targets);
    k_edge    <<<512, 128>>>();
    k_phase2  <<<512, 128>>>();
    k_zmin    <<<512, 128>>>();
    k_final   <<<1, 32>>>(out);
}

// round 8
// speedup vs baseline: 15.4628x; 1.2268x over previous
#include <cuda_runtime.h>
#include <math_constants.h>

// Hausdorff distance between edge sets of two binary 128^3 masks, batch=2.
// Pipeline: bit-pack masks -> bitwise 3x3x3 edge extraction fused with exact
// 1D x-distance g (u8) -> Meijster envelope along y producing dt2 = exact 2D
// squared EDT per z-slice (u16) -> per partner edge voxel, exact min over z
// using a precomputed radius bound (independent loads, no serial chain) ->
// directed max -> sqrt. Output: 2 floats.

#define DWH 128
#define NVOL 4                      // (b0,in) (b0,tgt) (b1,in) (b1,tgt)
#define VOXELS (128 * 128 * 128)
#define GCLAMP 222                  // 222^2 = 49284 > 3*127^2 -> lossless clamp

// ---- scratch: __device__ globals (no allocation allowed) ----
__device__ unsigned int   g_mask[NVOL][DWH][DWH][4];  // bit-packed masks, 1MB
__device__ unsigned int   g_edge[NVOL][DWH][DWH][4];  // bit-packed edges, 1MB
__device__ unsigned int   g_g[NVOL][DWH][DWH][32];    // 1D x-dist u8[128]/row, 8MB
__device__ unsigned short g_dt2[NVOL][VOXELS];        // 2D sq-EDT per slice, 16MB
__device__ int            g_cnt[NVOL];                // edge voxel counts
__device__ int            g_dirmax[NVOL];             // directed max squared EDT
__device__ unsigned int   g_done;                     // k_zmin completion counter

// ============================================================================
// Kernel 1: binarize inputs (>0) into bit-packed masks via warp ballot.
// Also zeroes the accumulators (consumed only by later kernels).
// ============================================================================
__global__ void __launch_bounds__(256) k_binarize(
    const float* __restrict__ inputs, const float* __restrict__ targets)
{
    int gt = blockIdx.x * blockDim.x + threadIdx.x;   // 8,388,608 threads
    if (gt < 9) {
        if (gt < 4)      g_cnt[gt] = 0;
        else if (gt < 8) g_dirmax[gt - 4] = 0;
        else             g_done = 0;
    }
    int lane = gt & 31;
    int c    = gt >> 5;              // chunk id, one warp each
    int v    = c >> 16;
    int rem  = c & 65535;
    int z    = rem >> 9;
    int y    = (rem >> 2) & 127;
    int w    = rem & 3;
    int x    = (w << 5) + lane;

    const float* src = (v & 1) ? targets : inputs;
    int b = v >> 1;
    float val = src[(size_t)b * VOXELS + z * 16384 + y * 128 + x];
    unsigned int bal = __ballot_sync(0xFFFFFFFFu, val > 0.0f);
    if (lane == 0) g_mask[v][z][y][w] = bal;
}

// ============================================================================
// Kernel 2: edge = (~mask) & (3x3x3 box-OR of mask), bitwise per (v,z,y) row,
// FUSED with the exact 1D distance-to-nearest-edge along x (g, u8 clamped).
// g stays entirely in registers (fully unrolled byte-packed array).
// Also accumulates edge-voxel counts (emptiness check).   [validated R3/R5]
// ============================================================================
__global__ void __launch_bounds__(128) k_edge()
{
    int t = blockIdx.x * blockDim.x + threadIdx.x;    // 65536 rows
    int v = t >> 14;
    int z = (t >> 7) & 127;
    int y = t & 127;

    unsigned int a0 = 0, a1 = 0, a2 = 0, a3 = 0;
    #pragma unroll
    for (int dz = -1; dz <= 1; dz++) {
        int zz = z + dz;
        if (zz < 0 || zz > 127) continue;
        #pragma unroll
        for (int dy = -1; dy <= 1; dy++) {
            int yy = y + dy;
            if (yy < 0 || yy > 127) continue;
            const unsigned int* r = g_mask[v][zz][yy];
            a0 |= r[0]; a1 |= r[1]; a2 |= r[2]; a3 |= r[3];
        }
    }
    // dilate along x across the 128-bit row (word carries)
    unsigned int d0 = a0 | (a0 << 1)               | (a0 >> 1) | (a1 << 31);
    unsigned int d1 = a1 | (a1 << 1) | (a0 >> 31)  | (a1 >> 1) | (a2 << 31);
    unsigned int d2 = a2 | (a2 << 1) | (a1 >> 31)  | (a2 >> 1) | (a3 << 31);
    unsigned int d3 = a3 | (a3 << 1) | (a2 >> 31)  | (a3 >> 1);

    const unsigned int* m = g_mask[v][z][y];
    unsigned int ew[4];
    ew[0] = d0 & ~m[0]; ew[1] = d1 & ~m[1]; ew[2] = d2 & ~m[2]; ew[3] = d3 & ~m[3];
    unsigned int* o = g_edge[v][z][y];
    o[0] = ew[0]; o[1] = ew[1]; o[2] = ew[2]; o[3] = ew[3];

    int cnt = __popc(ew[0]) + __popc(ew[1]) + __popc(ew[2]) + __popc(ew[3]);
    #pragma unroll
    for (int off = 16; off; off >>= 1)
        cnt += __shfl_down_sync(0xFFFFFFFFu, cnt, off);
    if ((threadIdx.x & 31) == 0) atomicAdd(&g_cnt[v], cnt);  // warp covers one v

    // ---- fused 1D x-distance g (exact, clamped at GCLAMP) ----
    unsigned int gr[32];                 // 128 u8 packed, static-indexed -> regs
    {
        int g = GCLAMP;
        #pragma unroll
        for (int w4 = 0; w4 < 32; w4++) {              // packs x = 4*w4 .. +3
            unsigned int word = ew[w4 >> 3];
            unsigned int packed = 0;
            #pragma unroll
            for (int j = 0; j < 4; j++) {
                int bit = (word >> (((w4 & 7) << 2) + j)) & 1;
                g = bit ? 0 : (g < GCLAMP ? g + 1 : GCLAMP);
                packed |= (unsigned int)g << (8 * j);
            }
            gr[w4] = packed;
        }
        int p = (gr[31] >> 24) & 0xFF;
        #pragma unroll
        for (int x = 126; x >= 0; x--) {
            int w4 = x >> 2, sh = (x & 3) << 3;
            int c = (gr[w4] >> sh) & 0xFF;
            int nv = p + 1;
            if (c < nv) nv = c;                        // nv <= GCLAMP always
            gr[w4] = (gr[w4] & ~(0xFFu << sh)) | ((unsigned int)nv << sh);
            p = nv;
        }
    }
    uint4* og = (uint4*)g_g[v][z][y];
    #pragma unroll
    for (int i = 0; i < 8; i++)
        og[i] = make_uint4(gr[4*i], gr[4*i+1], gr[4*i+2], gr[4*i+3]);
}

// ============================================================================
// Kernel 3: Meijster lower-envelope along y per (v,z,x) column.
//   dt2(x,y,z) = min_yy (y-yy)^2 + g(x,yy,z)^2   (exact 2D squared EDT)
// Stack TOP (sq,tq,fsq) register-cached; local stack touched only on push/pop.
// Max value = 127^2 + 222^2 = 65413 < 65536 -> u16 store needs no clamp.
// [validated in R5]
// ============================================================================
__global__ void __launch_bounds__(128) k_phase2()
{
    int b = blockIdx.x;                  // 512 = 4 volumes * 128 z-slices
    int v = b >> 7;
    int z = b & 127;
    int x = threadIdx.x;

    const unsigned char* grow = (const unsigned char*)g_g[v][z];  // [y][128] u8

    short          stS[128];             // stored stack below the register top
    short          stT[128];
    unsigned short stF[128];

    int q  = 0;                          // top level; stack[0..q-1] in memory
    int sq = 0, tq = 0;
    int g0 = grow[x];
    int fsq = g0 * g0;

    #pragma unroll 4
    for (int u = 1; u < 128; u++) {
        int gu = grow[u * 128 + x];
        int fu = gu * gu;
        for (;;) {
            int aa = tq - sq, bb = tq - u;
            if (aa * aa + fsq > bb * bb + fu) {       // incumbent loses at tq
                if (q == 0) { q = -1; break; }
                q--; sq = stS[q]; tq = stT[q]; fsq = stF[q];
            } else break;
        }
        if (q < 0) { q = 0; sq = u; tq = 0; fsq = fu; }
        else {
            int w = 1 + (u * u - sq * sq + fu - fsq) / (2 * (u - sq));
            if (w < 128) {
                stS[q] = (short)sq; stT[q] = (short)tq; stF[q] = (unsigned short)fsq;
                q++; sq = u; tq = w; fsq = fu;
            }
        }
    }

    unsigned short* dt = &g_dt2[v][z * 16384 + x];
    #pragma unroll 4
    for (int u = 127; u >= 0; u--) {
        int d = u - sq;
        dt[u * 128] = (unsigned short)(d * d + fsq);
        if (u == tq) {
            q--;
            if (q >= 0) { sq = stS[q]; tq = stT[q]; fsq = stF[q]; }
        }
    }
}

// ============================================================================
// Kernel 4: z-min gather + finalize. For each edge voxel q=(x,y,z) of qv:
//   EDT(q) = min_zz (z-zz)^2 + dt2_pv(x,y,zz)
// best0 = dt2_pv at zz=z (exact in-slice EDT) bounds the radius BEFORE the
// scan: dzmax = floor(sqrt(best0))+1 (overshoot harmless, undershoot
// impossible). The zz loop then has NO value-dependent exits -> independent,
// pipelined loads. Directed max -> atomicMax; last finished block computes
// the final two outputs (atomic reads of g_dirmax avoid a stale L1 line
// shared with g_cnt).
// Grid = (qv, z, y-quarter) = 2048 blocks; 128 threads = x.
// ============================================================================
__global__ void __launch_bounds__(128) k_zmin(float* __restrict__ out)
{
    int b  = blockIdx.x;                 // 2048
    int qv = b >> 9;
    int z  = (b >> 2) & 127;
    int yq = b & 3;
    int x  = threadIdx.x;
    int pv = qv ^ 1;

    int lmax = -1;
    if (g_cnt[pv] != 0) {                // empty partner -> output is inf anyway
        int wid = x >> 5, lane = x & 31;
        const unsigned short* base = &g_dt2[pv][x];
        for (int yi = 0; yi < 32; yi++) {
            int y = (yq << 5) + yi;
            unsigned int eb = g_edge[qv][z][y][wid];   // warp-uniform word
            if (eb == 0) continue;                     // whole warp skips
            if (!((eb >> lane) & 1)) continue;         // inactive lane skips

            const unsigned short* col = base + y * 128;
            int best = (int)col[z * 16384];            // tight exact bound
            int dzmax = (int)sqrtf((float)best) + 1;   // safe overshoot
            int zlo = z - dzmax; if (zlo < 0) zlo = 0;
            int zhi = z + dzmax; if (zhi > 127) zhi = 127;
            #pragma unroll 4
            for (int zz = zlo; zz <= zhi; zz++) {
                int d = z - zz;
                int c = d * d + (int)col[zz * 16384];  // independent loads
                if (c < best) best = c;
            }
            if (best > lmax) lmax = best;
        }
    }

    // block max over 128 threads -> one atomic per block
    #pragma unroll
    for (int off = 16; off; off >>= 1) {
        int o = __shfl_down_sync(0xFFFFFFFFu, lmax, off);
        if (o > lmax) lmax = o;
    }
    __shared__ int wmax[4];
    __shared__ int is_last;
    if ((x & 31) == 0) wmax[x >> 5] = lmax;
    __syncthreads();
    if (x == 0) {
        int m = wmax[0];
        if (wmax[1] > m) m = wmax[1];
        if (wmax[2] > m) m = wmax[2];
        if (wmax[3] > m) m = wmax[3];
        if (m >= 0) atomicMax(&g_dirmax[qv], m);
        __threadfence();
        unsigned int d = atomicAdd(&g_done, 1u);
        is_last = (d == (unsigned int)(gridDim.x - 1));
    }
    __syncthreads();
    if (is_last && x < 2) {              // last block finalizes both outputs
        int vA = 2 * x, vB = 2 * x + 1;
        bool empty = (g_cnt[vA] == 0) || (g_cnt[vB] == 0);
        int mA = atomicAdd(&g_dirmax[vA], 0);   // L2 read (bypass stale L1)
        int mB = atomicAdd(&g_dirmax[vB], 0);
        int m  = mA > mB ? mA : mB;
        out[x] = empty ? CUDART_INF_F : sqrtf((float)m);
    }
}

// ============================================================================
extern "C" void kernel_launch(void* const* d_in, const int* in_sizes, int n_in,
                              void* d_out, int out_size)
{
    const float* inputs  = (const float*)d_in[0];
    const float* targets = (const float*)d_in[1];
    float* out = (float*)d_out;

    k_binarize<<<32768, 256>>>(inputs, targets);
    k_edge    <<<512, 128>>>();
    k_phase2  <<<512, 128>>>();
    k_zmin    <<<2048, 128>>>(out);
}

// round 10
// speedup vs baseline: 32.6235x; 2.1098x over previous
#include <cuda_runtime.h>
#include <math_constants.h>

// Hausdorff distance between edge sets of two binary 128^3 masks, batch=2.
// Pipeline: bit-pack masks -> bitwise 3x3x3 edge extraction fused with exact
// 1D x-distance g (u8) AND edge-voxel worklist compaction -> Meijster
// envelope along y producing dt2 = exact 2D squared EDT per z-slice (u16) ->
// one thread per partner edge voxel: exact min over z within a precomputed
// radius bound -> directed max -> sqrt. Output: 2 floats.

#define DWH 128
#define NVOL 4                      // (b0,in) (b0,tgt) (b1,in) (b1,tgt)
#define VOXELS (128 * 128 * 128)
#define GCLAMP 222                  // 222^2 = 49284 > 3*127^2 -> lossless clamp

// ---- scratch: __device__ globals (no allocation allowed) ----
__device__ unsigned int   g_mask[NVOL][DWH][DWH][4];  // bit-packed masks, 1MB
__device__ unsigned int   g_g[NVOL][DWH][DWH][32];    // 1D x-dist u8[128]/row, 8MB
__device__ unsigned short g_dt2[NVOL][VOXELS];        // 2D sq-EDT per slice, 16MB
__device__ unsigned int   g_list[NVOL][VOXELS];       // packed edge coords, 32MB
__device__ int            g_cnt[NVOL];                // edge counts / list sizes
__device__ int            g_dirmax[NVOL];             // directed max squared EDT
__device__ unsigned int   g_done;                     // k_zmin completion counter

// ============================================================================
// Kernel 1: binarize inputs (>0) into bit-packed masks via warp ballot.
// Also zeroes the accumulators (consumed only by later kernels).
// ============================================================================
__global__ void __launch_bounds__(256) k_binarize(
    const float* __restrict__ inputs, const float* __restrict__ targets)
{
    int gt = blockIdx.x * blockDim.x + threadIdx.x;   // 8,388,608 threads
    if (gt < 9) {
        if (gt < 4)      g_cnt[gt] = 0;
        else if (gt < 8) g_dirmax[gt - 4] = 0;
        else             g_done = 0;
    }
    int lane = gt & 31;
    int c    = gt >> 5;              // chunk id, one warp each
    int v    = c >> 16;
    int rem  = c & 65535;
    int z    = rem >> 9;
    int y    = (rem >> 2) & 127;
    int w    = rem & 3;
    int x    = (w << 5) + lane;

    const float* src = (v & 1) ? targets : inputs;
    int b = v >> 1;
    float val = src[(size_t)b * VOXELS + z * 16384 + y * 128 + x];
    unsigned int bal = __ballot_sync(0xFFFFFFFFu, val > 0.0f);
    if (lane == 0) g_mask[v][z][y][w] = bal;
}

// ============================================================================
// Kernel 2: edge = (~mask) & (3x3x3 box-OR of mask), bitwise per (v,z,y) row,
// FUSED with (a) the exact 1D x-distance g (u8, register byte-array) and
// (b) edge-voxel worklist compaction: one atomicAdd range reservation per
// row, then packed coords (z<<14|y<<7|x) appended x-ascending -> consecutive
// list entries are x-adjacent (coalesced consumers). [core validated R3-R8]
// ============================================================================
__global__ void __launch_bounds__(128) k_edge()
{
    int t = blockIdx.x * blockDim.x + threadIdx.x;    // 65536 rows
    int v = t >> 14;
    int z = (t >> 7) & 127;
    int y = t & 127;

    unsigned int a0 = 0, a1 = 0, a2 = 0, a3 = 0;
    #pragma unroll
    for (int dz = -1; dz <= 1; dz++) {
        int zz = z + dz;
        if (zz < 0 || zz > 127) continue;
        #pragma unroll
        for (int dy = -1; dy <= 1; dy++) {
            int yy = y + dy;
            if (yy < 0 || yy > 127) continue;
            const unsigned int* r = g_mask[v][zz][yy];
            a0 |= r[0]; a1 |= r[1]; a2 |= r[2]; a3 |= r[3];
        }
    }
    // dilate along x across the 128-bit row (word carries)
    unsigned int d0 = a0 | (a0 << 1)               | (a0 >> 1) | (a1 << 31);
    unsigned int d1 = a1 | (a1 << 1) | (a0 >> 31)  | (a1 >> 1) | (a2 << 31);
    unsigned int d2 = a2 | (a2 << 1) | (a1 >> 31)  | (a2 >> 1) | (a3 << 31);
    unsigned int d3 = a3 | (a3 << 1) | (a2 >> 31)  | (a3 >> 1);

    const unsigned int* m = g_mask[v][z][y];
    unsigned int ew[4];
    ew[0] = d0 & ~m[0]; ew[1] = d1 & ~m[1]; ew[2] = d2 & ~m[2]; ew[3] = d3 & ~m[3];

    // ---- worklist append (one reservation per row with any edges) ----
    int cnt = __popc(ew[0]) + __popc(ew[1]) + __popc(ew[2]) + __popc(ew[3]);
    if (cnt) {
        int idx = atomicAdd(&g_cnt[v], cnt);
        unsigned int* lst = g_list[v];
        unsigned int zy = ((unsigned int)z << 14) | ((unsigned int)y << 7);
        #pragma unroll
        for (int w = 0; w < 4; w++) {
            unsigned int bits = ew[w];
            while (bits) {
                int bit = __ffs(bits) - 1;
                bits &= bits - 1;
                lst[idx++] = zy | (unsigned int)(w * 32 + bit);
            }
        }
    }

    // ---- fused 1D x-distance g (exact, clamped at GCLAMP) ----
    unsigned int gr[32];                 // 128 u8 packed, static-indexed -> regs
    {
        int g = GCLAMP;
        #pragma unroll
        for (int w4 = 0; w4 < 32; w4++) {              // packs x = 4*w4 .. +3
            unsigned int word = ew[w4 >> 3];
            unsigned int packed = 0;
            #pragma unroll
            for (int j = 0; j < 4; j++) {
                int bit = (word >> (((w4 & 7) << 2) + j)) & 1;
                g = bit ? 0 : (g < GCLAMP ? g + 1 : GCLAMP);
                packed |= (unsigned int)g << (8 * j);
            }
            gr[w4] = packed;
        }
        int p = (gr[31] >> 24) & 0xFF;
        #pragma unroll
        for (int x = 126; x >= 0; x--) {
            int w4 = x >> 2, sh = (x & 3) << 3;
            int c = (gr[w4] >> sh) & 0xFF;
            int nv = p + 1;
            if (c < nv) nv = c;                        // nv <= GCLAMP always
            gr[w4] = (gr[w4] & ~(0xFFu << sh)) | ((unsigned int)nv << sh);
            p = nv;
        }
    }
    uint4* og = (uint4*)g_g[v][z][y];
    #pragma unroll
    for (int i = 0; i < 8; i++)
        og[i] = make_uint4(gr[4*i], gr[4*i+1], gr[4*i+2], gr[4*i+3]);
}

// ============================================================================
// Kernel 3: Meijster lower-envelope along y per (v,z,x) column.
//   dt2(x,y,z) = min_yy (y-yy)^2 + g(x,yy,z)^2   (exact 2D squared EDT)
// Stack TOP (sq,tq,fsq) register-cached; local stack touched only on push/pop.
// Max value = 127^2 + 222^2 = 65413 < 65536 -> u16 store needs no clamp.
// [validated R5/R8]
// ============================================================================
__global__ void __launch_bounds__(128) k_phase2()
{
    int b = blockIdx.x;                  // 512 = 4 volumes * 128 z-slices
    int v = b >> 7;
    int z = b & 127;
    int x = threadIdx.x;

    const unsigned char* grow = (const unsigned char*)g_g[v][z];  // [y][128] u8

    short          stS[128];             // stored stack below the register top
    short          stT[128];
    unsigned short stF[128];

    int q  = 0;                          // top level; stack[0..q-1] in memory
    int sq = 0, tq = 0;
    int g0 = grow[x];
    int fsq = g0 * g0;

    #pragma unroll 4
    for (int u = 1; u < 128; u++) {
        int gu = grow[u * 128 + x];
        int fu = gu * gu;
        for (;;) {
            int aa = tq - sq, bb = tq - u;
            if (aa * aa + fsq > bb * bb + fu) {       // incumbent loses at tq
                if (q == 0) { q = -1; break; }
                q--; sq = stS[q]; tq = stT[q]; fsq = stF[q];
            } else break;
        }
        if (q < 0) { q = 0; sq = u; tq = 0; fsq = fu; }
        else {
            int w = 1 + (u * u - sq * sq + fu - fsq) / (2 * (u - sq));
            if (w < 128) {
                stS[q] = (short)sq; stT[q] = (short)tq; stF[q] = (unsigned short)fsq;
                q++; sq = u; tq = w; fsq = fu;
            }
        }
    }

    unsigned short* dt = &g_dt2[v][z * 16384 + x];
    #pragma unroll 4
    for (int u = 127; u >= 0; u--) {
        int d = u - sq;
        dt[u * 128] = (unsigned short)(d * d + fsq);
        if (u == tq) {
            q--;
            if (q >= 0) { sq = stS[q]; tq = stT[q]; fsq = stF[q]; }
        }
    }
}

// ============================================================================
// Kernel 4: one thread per partner edge voxel (grid-stride over the compacted
// worklist). For voxel q=(x,y,z) of volume qv:
//   EDT(q) = min_zz (z-zz)^2 + dt2_pv(x,y,zz)
// best0 = dt2_pv at zz=z is the exact in-slice EDT -> radius bound
// dzmax = floor(sqrt(best0))+1 (overshoot harmless). All threads independent;
// no per-row serial chain. Directed max -> atomicMax; last finished block
// writes both outputs (atomic reads bypass a stale L1 line shared w/ g_cnt).
// Grid = 1024 blocks x 128 thr; qv = blockIdx&3, 32768 threads per volume.
// ============================================================================
__global__ void __launch_bounds__(128) k_zmin(float* __restrict__ out)
{
    int b   = blockIdx.x;                // 1024
    int qv  = b & 3;
    int pv  = qv ^ 1;
    int tid = threadIdx.x;

    int cnt = g_cnt[qv];                 // list size for this volume
    int lmax = -1;
    const unsigned int*   lst  = g_list[qv];
    const unsigned short* dtpv = g_dt2[pv];

    for (int i = (b >> 2) * 128 + tid; i < cnt; i += 256 * 128) {
        unsigned int e = lst[i];
        int x = e & 127;
        int y = (int)(e >> 7) & 127;
        int z = (int)(e >> 14);

        const unsigned short* col = dtpv + y * 128 + x;
        int best = (int)col[z * 16384];            // tight exact bound (dz=0)
        int dzmax = (int)sqrtf((float)best) + 1;   // safe overshoot
        int zlo = z - dzmax; if (zlo < 0) zlo = 0;
        int zhi = z + dzmax; if (zhi > 127) zhi = 127;
        #pragma unroll 4
        for (int zz = zlo; zz <= zhi; zz++) {
            int d = z - zz;
            int c = d * d + (int)col[zz * 16384];  // independent loads
            if (c < best) best = c;
        }
        if (best > lmax) lmax = best;
    }

    // block max over 128 threads -> one atomic per block
    #pragma unroll
    for (int off = 16; off; off >>= 1) {
        int o = __shfl_down_sync(0xFFFFFFFFu, lmax, off);
        if (o > lmax) lmax = o;
    }
    __shared__ int wmax[4];
    __shared__ int is_last;
    if ((tid & 31) == 0) wmax[tid >> 5] = lmax;
    __syncthreads();
    if (tid == 0) {
        int m = wmax[0];
        if (wmax[1] > m) m = wmax[1];
        if (wmax[2] > m) m = wmax[2];
        if (wmax[3] > m) m = wmax[3];
        if (m >= 0) atomicMax(&g_dirmax[qv], m);
        __threadfence();
        unsigned int d = atomicAdd(&g_done, 1u);
        is_last = (d == (unsigned int)(gridDim.x - 1));
    }
    __syncthreads();
    if (is_last && tid < 2) {            // last block finalizes both outputs
        int vA = 2 * tid, vB = 2 * tid + 1;
        bool empty = (g_cnt[vA] == 0) || (g_cnt[vB] == 0);
        int mA = atomicAdd(&g_dirmax[vA], 0);   // L2 read (bypass stale L1)
        int mB = atomicAdd(&g_dirmax[vB], 0);
        int m  = mA > mB ? mA : mB;
        out[tid] = empty ? CUDART_INF_F : sqrtf((float)m);
    }
}

// ============================================================================
extern "C" void kernel_launch(void* const* d_in, const int* in_sizes, int n_in,
                              void* d_out, int out_size)
{
    const float* inputs  = (const float*)d_in[0];
    const float* targets = (const float*)d_in[1];
    float* out = (float*)d_out;

    k_binarize<<<32768, 256>>>(inputs, targets);
    k_edge    <<<512, 128>>>();
    k_phase2  <<<512, 128>>>();
    k_zmin    <<<1024, 128>>>(out);
}

// round 11
// speedup vs baseline: 40.8844x; 1.2532x over previous
#include <cuda_runtime.h>
#include <math_constants.h>

// Hausdorff distance between edge sets of two binary 128^3 masks, batch=2.
// Pipeline: bit-pack masks -> [fused] bitwise 3x3x3 edge extraction + exact
// 1D x-distance g (u8, via smem slice) + edge-voxel worklist compaction +
// Meijster envelope along y -> dt2 = exact 2D squared EDT per z-slice (u16)
// -> one thread per partner edge voxel: exact min over z within a
// precomputed radius bound -> directed max -> sqrt. Output: 2 floats.

#define DWH 128
#define NVOL 4                      // (b0,in) (b0,tgt) (b1,in) (b1,tgt)
#define VOXELS (128 * 128 * 128)
#define GCLAMP 222                  // 222^2 = 49284 > 3*127^2 -> lossless clamp
#define GPITCH 132                  // smem g row pitch (33 words, stride 1 bank)

// ---- scratch: __device__ globals (no allocation allowed) ----
__device__ unsigned int   g_mask[NVOL][DWH][DWH][4];  // bit-packed masks, 1MB
__device__ unsigned short g_dt2[NVOL][VOXELS];        // 2D sq-EDT per slice, 16MB
__device__ unsigned int   g_list[NVOL][VOXELS];       // packed edge coords, 32MB
__device__ int            g_cnt[NVOL];                // edge counts / list sizes
__device__ int            g_dirmax[NVOL];             // directed max squared EDT
__device__ unsigned int   g_done;                     // k_zmin completion counter

// ============================================================================
// Kernel 1: binarize inputs (>0) into bit-packed masks via warp ballot.
// Also zeroes the accumulators (consumed only by later kernels).
// [validated R2-R10]
// ============================================================================
__global__ void __launch_bounds__(256) k_binarize(
    const float* __restrict__ inputs, const float* __restrict__ targets)
{
    int gt = blockIdx.x * blockDim.x + threadIdx.x;   // 8,388,608 threads
    if (gt < 9) {
        if (gt < 4)      g_cnt[gt] = 0;
        else if (gt < 8) g_dirmax[gt - 4] = 0;
        else             g_done = 0;
    }
    int lane = gt & 31;
    int c    = gt >> 5;              // chunk id, one warp each
    int v    = c >> 16;
    int rem  = c & 65535;
    int z    = rem >> 9;
    int y    = (rem >> 2) & 127;
    int w    = rem & 3;
    int x    = (w << 5) + lane;

    const float* src = (v & 1) ? targets : inputs;
    int b = v >> 1;
    float val = src[(size_t)b * VOXELS + z * 16384 + y * 128 + x];
    unsigned int bal = __ballot_sync(0xFFFFFFFFu, val > 0.0f);
    if (lane == 0) g_mask[v][z][y][w] = bal;
}

// ============================================================================
// Kernel 2 (FUSED edge + phase2), one block per (v,z) slice, 128 threads.
// Stage A (thread = y-row): edge = (~mask) & (3x3x3 box-OR of mask) bitwise;
//   worklist append (one atomicAdd range reservation per row, x-ascending ->
//   coalesced consumers); exact 1D x-distance g (u8, register byte-array)
//   staged into a smem slice [y][x] (pitch 132: conflict-free both ways).
// Stage B (thread = x-column): Meijster lower envelope along y over smem g:
//   dt2(x,y,z) = min_yy (y-yy)^2 + g(x,yy,z)^2  (exact 2D squared EDT).
//   Stack TOP (sq,tq,fsq) register-cached. Max dt2 = 127^2+222^2 = 65413
//   < 65536 -> u16 store needs no clamp.
// [edge math / append / envelope byte-identical to the R10 passing kernel]
// ============================================================================
__global__ void __launch_bounds__(128) k_edgephase2()
{
    __shared__ unsigned char gsm[128 * GPITCH];       // 16.9 KB g slice [y][x]

    int b = blockIdx.x;                  // 512 = 4 volumes * 128 z-slices
    int v = b >> 7;
    int z = b & 127;
    int y = threadIdx.x;                 // stage A: thread = y-row

    // ---- stage A: edge bits for row (v,z,y) ----
    unsigned int a0 = 0, a1 = 0, a2 = 0, a3 = 0;
    #pragma unroll
    for (int dz = -1; dz <= 1; dz++) {
        int zz = z + dz;
        if (zz < 0 || zz > 127) continue;
        #pragma unroll
        for (int dy = -1; dy <= 1; dy++) {
            int yy = y + dy;
            if (yy < 0 || yy > 127) continue;
            const unsigned int* r = g_mask[v][zz][yy];
            a0 |= r[0]; a1 |= r[1]; a2 |= r[2]; a3 |= r[3];
        }
    }
    // dilate along x across the 128-bit row (word carries)
    unsigned int d0 = a0 | (a0 << 1)               | (a0 >> 1) | (a1 << 31);
    unsigned int d1 = a1 | (a1 << 1) | (a0 >> 31)  | (a1 >> 1) | (a2 << 31);
    unsigned int d2 = a2 | (a2 << 1) | (a1 >> 31)  | (a2 >> 1) | (a3 << 31);
    unsigned int d3 = a3 | (a3 << 1) | (a2 >> 31)  | (a3 >> 1);

    const unsigned int* m = g_mask[v][z][y];
    unsigned int ew[4];
    ew[0] = d0 & ~m[0]; ew[1] = d1 & ~m[1]; ew[2] = d2 & ~m[2]; ew[3] = d3 & ~m[3];

    // ---- worklist append (one reservation per row with any edges) ----
    int cnt = __popc(ew[0]) + __popc(ew[1]) + __popc(ew[2]) + __popc(ew[3]);
    if (cnt) {
        int idx = atomicAdd(&g_cnt[v], cnt);
        unsigned int* lst = g_list[v];
        unsigned int zy = ((unsigned int)z << 14) | ((unsigned int)y << 7);
        #pragma unroll
        for (int w = 0; w < 4; w++) {
            unsigned int bits = ew[w];
            while (bits) {
                int bit = __ffs(bits) - 1;
                bits &= bits - 1;
                lst[idx++] = zy | (unsigned int)(w * 32 + bit);
            }
        }
    }

    // ---- 1D x-distance g (exact, clamped at GCLAMP), registers -> smem ----
    unsigned int gr[32];                 // 128 u8 packed, static-indexed -> regs
    {
        int g = GCLAMP;
        #pragma unroll
        for (int w4 = 0; w4 < 32; w4++) {              // packs x = 4*w4 .. +3
            unsigned int word = ew[w4 >> 3];
            unsigned int packed = 0;
            #pragma unroll
            for (int j = 0; j < 4; j++) {
                int bit = (word >> (((w4 & 7) << 2) + j)) & 1;
                g = bit ? 0 : (g < GCLAMP ? g + 1 : GCLAMP);
                packed |= (unsigned int)g << (8 * j);
            }
            gr[w4] = packed;
        }
        int p = (gr[31] >> 24) & 0xFF;
        #pragma unroll
        for (int x = 126; x >= 0; x--) {
            int w4 = x >> 2, sh = (x & 3) << 3;
            int c = (gr[w4] >> sh) & 0xFF;
            int nv = p + 1;
            if (c < nv) nv = c;                        // nv <= GCLAMP always
            gr[w4] = (gr[w4] & ~(0xFFu << sh)) | ((unsigned int)nv << sh);
            p = nv;
        }
    }
    {
        unsigned int* row = (unsigned int*)&gsm[y * GPITCH];  // 132 % 4 == 0
        #pragma unroll
        for (int i = 0; i < 32; i++) row[i] = gr[i];   // stride-33-word: no bank conflicts
    }
    __syncthreads();

    // ---- stage B: Meijster envelope along y, thread = x column ----
    {
        int x = threadIdx.x;
        const unsigned char* gcol = &gsm[x];

        short          stS[128];         // stored stack below the register top
        short          stT[128];
        unsigned short stF[128];

        int q  = 0;                      // top level; stack[0..q-1] in memory
        int sq = 0, tq = 0;
        int g0 = gcol[0];
        int fsq = g0 * g0;

        #pragma unroll 4
        for (int u = 1; u < 128; u++) {
            int gu = gcol[u * GPITCH];
            int fu = gu * gu;
            for (;;) {
                int aa = tq - sq, bb = tq - u;
                if (aa * aa + fsq > bb * bb + fu) {    // incumbent loses at tq
                    if (q == 0) { q = -1; break; }
                    q--; sq = stS[q]; tq = stT[q]; fsq = stF[q];
                } else break;
            }
            if (q < 0) { q = 0; sq = u; tq = 0; fsq = fu; }
            else {
                int w = 1 + (u * u - sq * sq + fu - fsq) / (2 * (u - sq));
                if (w < 128) {
                    stS[q] = (short)sq; stT[q] = (short)tq; stF[q] = (unsigned short)fsq;
                    q++; sq = u; tq = w; fsq = fu;
                }
            }
        }

        unsigned short* dt = &g_dt2[v][z * 16384 + x];
        #pragma unroll 4
        for (int u = 127; u >= 0; u--) {
            int d = u - sq;
            dt[u * 128] = (unsigned short)(d * d + fsq);
            if (u == tq) {
                q--;
                if (q >= 0) { sq = stS[q]; tq = stT[q]; fsq = stF[q]; }
            }
        }
    }
}

// ============================================================================
// Kernel 3: one thread per partner edge voxel (grid-stride over the compacted
// worklist). For voxel q=(x,y,z) of volume qv:
//   EDT(q) = min_zz (z-zz)^2 + dt2_pv(x,y,zz)
// best0 = dt2_pv at zz=z is the exact in-slice EDT -> radius bound
// dzmax = floor(sqrt(best0))+1 (overshoot harmless). All threads independent.
// Directed max -> atomicMax; last finished block writes both outputs
// (atomic reads bypass a stale L1 line shared with g_cnt).
// [validated R10: 21.6us]
// ============================================================================
__global__ void __launch_bounds__(128) k_zmin(float* __restrict__ out)
{
    int b   = blockIdx.x;                // 1024
    int qv  = b & 3;
    int pv  = qv ^ 1;
    int tid = threadIdx.x;

    int cnt = g_cnt[qv];                 // list size for this volume
    int lmax = -1;
    const unsigned int*   lst  = g_list[qv];
    const unsigned short* dtpv = g_dt2[pv];

    for (int i = (b >> 2) * 128 + tid; i < cnt; i += 256 * 128) {
        unsigned int e = lst[i];
        int x = e & 127;
        int y = (int)(e >> 7) & 127;
        int z = (int)(e >> 14);

        const unsigned short* col = dtpv + y * 128 + x;
        int best = (int)col[z * 16384];            // tight exact bound (dz=0)
        int dzmax = (int)sqrtf((float)best) + 1;   // safe overshoot
        int zlo = z - dzmax; if (zlo < 0) zlo = 0;
        int zhi = z + dzmax; if (zhi > 127) zhi = 127;
        #pragma unroll 4
        for (int zz = zlo; zz <= zhi; zz++) {
            int d = z - zz;
            int c = d * d + (int)col[zz * 16384];  // independent loads
            if (c < best) best = c;
        }
        if (best > lmax) lmax = best;
    }

    // block max over 128 threads -> one atomic per block
    #pragma unroll
    for (int off = 16; off; off >>= 1) {
        int o = __shfl_down_sync(0xFFFFFFFFu, lmax, off);
        if (o > lmax) lmax = o;
    }
    __shared__ int wmax[4];
    __shared__ int is_last;
    if ((tid & 31) == 0) wmax[tid >> 5] = lmax;
    __syncthreads();
    if (tid == 0) {
        int m = wmax[0];
        if (wmax[1] > m) m = wmax[1];
        if (wmax[2] > m) m = wmax[2];
        if (wmax[3] > m) m = wmax[3];
        if (m >= 0) atomicMax(&g_dirmax[qv], m);
        __threadfence();
        unsigned int d = atomicAdd(&g_done, 1u);
        is_last = (d == (unsigned int)(gridDim.x - 1));
    }
    __syncthreads();
    if (is_last && tid < 2) {            // last block finalizes both outputs
        int vA = 2 * tid, vB = 2 * tid + 1;
        bool empty = (g_cnt[vA] == 0) || (g_cnt[vB] == 0);
        int mA = atomicAdd(&g_dirmax[vA], 0);   // L2 read (bypass stale L1)
        int mB = atomicAdd(&g_dirmax[vB], 0);
        int m  = mA > mB ? mA : mB;
        out[tid] = empty ? CUDART_INF_F : sqrtf((float)m);
    }
}

// ============================================================================
extern "C" void kernel_launch(void* const* d_in, const int* in_sizes, int n_in,
                              void* d_out, int out_size)
{
    const float* inputs  = (const float*)d_in[0];
    const float* targets = (const float*)d_in[1];
    float* out = (float*)d_out;

    k_binarize   <<<32768, 256>>>(inputs, targets);
    k_edgephase2 <<<512, 128>>>();
    k_zmin       <<<1024, 128>>>(out);
}

// round 12
// speedup vs baseline: 46.3837x; 1.1345x over previous
#include <cuda_runtime.h>
#include <math_constants.h>

// Hausdorff distance between edge sets of two binary 128^3 masks, batch=2.
// Pipeline: bit-pack masks (float4 + shfl-assembled words) -> [fused] bitwise
// 3x3x3 edge extraction + exact 1D x-distance g (u8, via smem slice) +
// edge-voxel worklist compaction + Meijster envelope along y -> dt2 = exact
// 2D squared EDT per z-slice (u16) -> one thread per partner edge voxel:
// exact min over z within a precomputed radius bound -> directed max ->
// sqrt. Output: 2 floats.

#define DWH 128
#define NVOL 4                      // (b0,in) (b0,tgt) (b1,in) (b1,tgt)
#define VOXELS (128 * 128 * 128)
#define GCLAMP 222                  // 222^2 = 49284 > 3*127^2 -> lossless clamp
#define GPITCH 132                  // smem g row pitch (33 words, stride 1 bank)

// ---- scratch: __device__ globals (no allocation allowed) ----
__device__ unsigned int   g_mask[NVOL][DWH][DWH][4];  // bit-packed masks, 1MB
__device__ unsigned short g_dt2[NVOL][VOXELS];        // 2D sq-EDT per slice, 16MB
__device__ unsigned int   g_list[NVOL][VOXELS];       // packed edge coords, 32MB
__device__ int            g_cnt[NVOL];                // edge counts / list sizes
__device__ int            g_dirmax[NVOL];             // directed max squared EDT
__device__ unsigned int   g_done;                     // k_zmin completion counter

// ============================================================================
// Kernel 1: binarize inputs (>0) into bit-packed masks.
// One warp per 128-float row; lane loads float4 (x = lane*4..+3) -> 4-bit
// nibble at bit (lane&7)*4 -> 3-step shfl_xor OR-reduce assembles each oct's
// 32-bit word -> lanes 0/8/16/24 store words 0..3. Word w bit j == mask at
// x = 32w+j (identical layout to the validated scalar-ballot version).
// Also zeroes the accumulators (consumed only by later kernels).
// ============================================================================
__global__ void __launch_bounds__(256) k_binarize(
    const float* __restrict__ inputs, const float* __restrict__ targets)
{
    int gt = blockIdx.x * blockDim.x + threadIdx.x;   // 2,097,152 threads
    if (gt < 9) {
        if (gt < 4)      g_cnt[gt] = 0;
        else if (gt < 8) g_dirmax[gt - 4] = 0;
        else             g_done = 0;
    }
    int lane = gt & 31;
    int wrp  = gt >> 5;              // 65536 warps, one per (v,z,y) row
    int v    = wrp >> 14;
    int rem  = wrp & 16383;
    int z    = rem >> 7;
    int y    = rem & 127;

    const float* src = (v & 1) ? targets : inputs;
    int b = v >> 1;
    const float4* row = (const float4*)(src + (size_t)b * VOXELS + z * 16384 + y * 128);
    float4 val = row[lane];

    unsigned int nib = (val.x > 0.0f ? 1u : 0u)
                     | (val.y > 0.0f ? 2u : 0u)
                     | (val.z > 0.0f ? 4u : 0u)
                     | (val.w > 0.0f ? 8u : 0u);
    unsigned int u = nib << ((lane & 7) * 4);
    u |= __shfl_xor_sync(0xFFFFFFFFu, u, 1);
    u |= __shfl_xor_sync(0xFFFFFFFFu, u, 2);
    u |= __shfl_xor_sync(0xFFFFFFFFu, u, 4);          // full word per 8-lane oct
    if ((lane & 7) == 0) g_mask[v][z][y][lane >> 3] = u;
}

// ============================================================================
// Kernel 2 (FUSED edge + phase2), one block per (v,z) slice, 128 threads.
// Stage A (thread = y-row): edge = (~mask) & (3x3x3 box-OR of mask) bitwise;
//   worklist append (one atomicAdd range reservation per row, x-ascending ->
//   coalesced consumers); exact 1D x-distance g (u8, register byte-array)
//   staged into a smem slice [y][x] (pitch 132: conflict-free both ways).
// Stage B (thread = x-column): Meijster lower envelope along y over smem g:
//   dt2(x,y,z) = min_yy (y-yy)^2 + g(x,yy,z)^2  (exact 2D squared EDT).
//   Stack TOP (sq,tq,fsq) register-cached. Max dt2 = 127^2+222^2 = 65413
//   < 65536 -> u16 store needs no clamp.    [byte-identical to R11 passing]
// ============================================================================
__global__ void __launch_bounds__(128) k_edgephase2()
{
    __shared__ unsigned char gsm[128 * GPITCH];       // 16.9 KB g slice [y][x]

    int b = blockIdx.x;                  // 512 = 4 volumes * 128 z-slices
    int v = b >> 7;
    int z = b & 127;
    int y = threadIdx.x;                 // stage A: thread = y-row

    // ---- stage A: edge bits for row (v,z,y) ----
    unsigned int a0 = 0, a1 = 0, a2 = 0, a3 = 0;
    #pragma unroll
    for (int dz = -1; dz <= 1; dz++) {
        int zz = z + dz;
        if (zz < 0 || zz > 127) continue;
        #pragma unroll
        for (int dy = -1; dy <= 1; dy++) {
            int yy = y + dy;
            if (yy < 0 || yy > 127) continue;
            const unsigned int* r = g_mask[v][zz][yy];
            a0 |= r[0]; a1 |= r[1]; a2 |= r[2]; a3 |= r[3];
        }
    }
    // dilate along x across the 128-bit row (word carries)
    unsigned int d0 = a0 | (a0 << 1)               | (a0 >> 1) | (a1 << 31);
    unsigned int d1 = a1 | (a1 << 1) | (a0 >> 31)  | (a1 >> 1) | (a2 << 31);
    unsigned int d2 = a2 | (a2 << 1) | (a1 >> 31)  | (a2 >> 1) | (a3 << 31);
    unsigned int d3 = a3 | (a3 << 1) | (a2 >> 31)  | (a3 >> 1);

    const unsigned int* m = g_mask[v][z][y];
    unsigned int ew[4];
    ew[0] = d0 & ~m[0]; ew[1] = d1 & ~m[1]; ew[2] = d2 & ~m[2]; ew[3] = d3 & ~m[3];

    // ---- worklist append (one reservation per row with any edges) ----
    int cnt = __popc(ew[0]) + __popc(ew[1]) + __popc(ew[2]) + __popc(ew[3]);
    if (cnt) {
        int idx = atomicAdd(&g_cnt[v], cnt);
        unsigned int* lst = g_list[v];
        unsigned int zy = ((unsigned int)z << 14) | ((unsigned int)y << 7);
        #pragma unroll
        for (int w = 0; w < 4; w++) {
            unsigned int bits = ew[w];
            while (bits) {
                int bit = __ffs(bits) - 1;
                bits &= bits - 1;
                lst[idx++] = zy | (unsigned int)(w * 32 + bit);
            }
        }
    }

    // ---- 1D x-distance g (exact, clamped at GCLAMP), registers -> smem ----
    unsigned int gr[32];                 // 128 u8 packed, static-indexed -> regs
    {
        int g = GCLAMP;
        #pragma unroll
        for (int w4 = 0; w4 < 32; w4++) {              // packs x = 4*w4 .. +3
            unsigned int word = ew[w4 >> 3];
            unsigned int packed = 0;
            #pragma unroll
            for (int j = 0; j < 4; j++) {
                int bit = (word >> (((w4 & 7) << 2) + j)) & 1;
                g = bit ? 0 : (g < GCLAMP ? g + 1 : GCLAMP);
                packed |= (unsigned int)g << (8 * j);
            }
            gr[w4] = packed;
        }
        int p = (gr[31] >> 24) & 0xFF;
        #pragma unroll
        for (int x = 126; x >= 0; x--) {
            int w4 = x >> 2, sh = (x & 3) << 3;
            int c = (gr[w4] >> sh) & 0xFF;
            int nv = p + 1;
            if (c < nv) nv = c;                        // nv <= GCLAMP always
            gr[w4] = (gr[w4] & ~(0xFFu << sh)) | ((unsigned int)nv << sh);
            p = nv;
        }
    }
    {
        unsigned int* row = (unsigned int*)&gsm[y * GPITCH];  // 132 % 4 == 0
        #pragma unroll
        for (int i = 0; i < 32; i++) row[i] = gr[i];   // stride-33-word: no bank conflicts
    }
    __syncthreads();

    // ---- stage B: Meijster envelope along y, thread = x column ----
    {
        int x = threadIdx.x;
        const unsigned char* gcol = &gsm[x];

        short          stS[128];         // stored stack below the register top
        short          stT[128];
        unsigned short stF[128];

        int q  = 0;                      // top level; stack[0..q-1] in memory
        int sq = 0, tq = 0;
        int g0 = gcol[0];
        int fsq = g0 * g0;

        #pragma unroll 4
        for (int u = 1; u < 128; u++) {
            int gu = gcol[u * GPITCH];
            int fu = gu * gu;
            for (;;) {
                int aa = tq - sq, bb = tq - u;
                if (aa * aa + fsq > bb * bb + fu) {    // incumbent loses at tq
                    if (q == 0) { q = -1; break; }
                    q--; sq = stS[q]; tq = stT[q]; fsq = stF[q];
                } else break;
            }
            if (q < 0) { q = 0; sq = u; tq = 0; fsq = fu; }
            else {
                int w = 1 + (u * u - sq * sq + fu - fsq) / (2 * (u - sq));
                if (w < 128) {
                    stS[q] = (short)sq; stT[q] = (short)tq; stF[q] = (unsigned short)fsq;
                    q++; sq = u; tq = w; fsq = fu;
                }
            }
        }

        unsigned short* dt = &g_dt2[v][z * 16384 + x];
        #pragma unroll 4
        for (int u = 127; u >= 0; u--) {
            int d = u - sq;
            dt[u * 128] = (unsigned short)(d * d + fsq);
            if (u == tq) {
                q--;
                if (q >= 0) { sq = stS[q]; tq = stT[q]; fsq = stF[q]; }
            }
        }
    }
}

// ============================================================================
// Kernel 3: one thread per partner edge voxel (grid-stride over the compacted
// worklist). For voxel q=(x,y,z) of volume qv:
//   EDT(q) = min_zz (z-zz)^2 + dt2_pv(x,y,zz)
// best0 = dt2_pv at zz=z is the exact in-slice EDT -> radius bound
// dzmax = floor(sqrt(best0))+1 (overshoot harmless). All threads independent.
// Directed max -> atomicMax; last finished block writes both outputs
// (atomic reads bypass a stale L1 line shared with g_cnt).
// [validated R10/R11: 21.6us]
// ============================================================================
__global__ void __launch_bounds__(128) k_zmin(float* __restrict__ out)
{
    int b   = blockIdx.x;                // 1024
    int qv  = b & 3;
    int pv  = qv ^ 1;
    int tid = threadIdx.x;

    int cnt = g_cnt[qv];                 // list size for this volume
    int lmax = -1;
    const unsigned int*   lst  = g_list[qv];
    const unsigned short* dtpv = g_dt2[pv];

    for (int i = (b >> 2) * 128 + tid; i < cnt; i += 256 * 128) {
        unsigned int e = lst[i];
        int x = e & 127;
        int y = (int)(e >> 7) & 127;
        int z = (int)(e >> 14);

        const unsigned short* col = dtpv + y * 128 + x;
        int best = (int)col[z * 16384];            // tight exact bound (dz=0)
        int dzmax = (int)sqrtf((float)best) + 1;   // safe overshoot
        int zlo = z - dzmax; if (zlo < 0) zlo = 0;
        int zhi = z + dzmax; if (zhi > 127) zhi = 127;
        #pragma unroll 4
        for (int zz = zlo; zz <= zhi; zz++) {
            int d = z - zz;
            int c = d * d + (int)col[zz * 16384];  // independent loads
            if (c < best) best = c;
        }
        if (best > lmax) lmax = best;
    }

    // block max over 128 threads -> one atomic per block
    #pragma unroll
    for (int off = 16; off; off >>= 1) {
        int o = __shfl_down_sync(0xFFFFFFFFu, lmax, off);
        if (o > lmax) lmax = o;
    }
    __shared__ int wmax[4];
    __shared__ int is_last;
    if ((tid & 31) == 0) wmax[tid >> 5] = lmax;
    __syncthreads();
    if (tid == 0) {
        int m = wmax[0];
        if (wmax[1] > m) m = wmax[1];
        if (wmax[2] > m) m = wmax[2];
        if (wmax[3] > m) m = wmax[3];
        if (m >= 0) atomicMax(&g_dirmax[qv], m);
        __threadfence();
        unsigned int d = atomicAdd(&g_done, 1u);
        is_last = (d == (unsigned int)(gridDim.x - 1));
    }
    __syncthreads();
    if (is_last && tid < 2) {            // last block finalizes both outputs
        int vA = 2 * tid, vB = 2 * tid + 1;
        bool empty = (g_cnt[vA] == 0) || (g_cnt[vB] == 0);
        int mA = atomicAdd(&g_dirmax[vA], 0);   // L2 read (bypass stale L1)
        int mB = atomicAdd(&g_dirmax[vB], 0);
        int m  = mA > mB ? mA : mB;
        out[tid] = empty ? CUDART_INF_F : sqrtf((float)m);
    }
}

// ============================================================================
extern "C" void kernel_launch(void* const* d_in, const int* in_sizes, int n_in,
                              void* d_out, int out_size)
{
    const float* inputs  = (const float*)d_in[0];
    const float* targets = (const float*)d_in[1];
    float* out = (float*)d_out;

    k_binarize   <<<8192, 256>>>(inputs, targets);
    k_edgephase2 <<<512, 128>>>();
    k_zmin       <<<1024, 128>>>(out);
}